// round 6
// baseline (speedup 1.0000x reference)
#include <cuda_runtime.h>

// Shapes (fixed by the problem): inputs [L,B,C,H,W] fp32, W [C,C] fp32
#define DL 4
#define DB 8
#define DC 256
#define DHW 4096             // 64*64
#define LBC (DL*DB*DC)       // 8192
#define VEC_PER_LBC 1024     // float4 per (l,b,c) row
#define GPB 512              // G blocks per batch (2 rows each; 1024 rows/batch)
#define MPB 1024             // M blocks per batch (1 row each)
#define SEG (MPB + GPB)      // 1536: one pipeline segment = M(b) + G(b+1), 2:1
#define TOTAL_BLOCKS (GPB + 7*SEG + MPB)  // 12288

__device__ float g_gap[LBC];
__device__ int   g_done[DB];

// ---------------------------------------------------------------------------
__global__ void init_kernel() {
    if (threadIdx.x < DB) g_done[threadIdx.x] = 0;
}

// ---------------------------------------------------------------------------
// G role: average-pool two consecutive rows (32KB contiguous DRAM read,
// MLP=8), publish gap, then release the per-batch flag.
// ---------------------------------------------------------------------------
__device__ __forceinline__ void gap_role(const float* __restrict__ in, int b, int j) {
    const int l  = j >> 7;                 // j in [0,512): 4 l x 128 c-pairs
    const int c  = (j & 127) * 2;
    const int g0 = (l * DB + b) * DC + c;

    const float4* base = reinterpret_cast<const float4*>(in) + (size_t)g0 * VEC_PER_LBC;
    const int t = threadIdx.x;

    float4 v[8];
#pragma unroll
    for (int i = 0; i < 8; ++i) v[i] = base[i * 256 + t];

    float s0 = 0.f, s1 = 0.f;
#pragma unroll
    for (int i = 0; i < 4; ++i) s0 += (v[i].x + v[i].y) + (v[i].z + v[i].w);
#pragma unroll
    for (int i = 4; i < 8; ++i) s1 += (v[i].x + v[i].y) + (v[i].z + v[i].w);

#pragma unroll
    for (int o = 16; o > 0; o >>= 1) {
        s0 += __shfl_xor_sync(0xffffffffu, s0, o);
        s1 += __shfl_xor_sync(0xffffffffu, s1, o);
    }

    __shared__ float ws[8][2];
    if ((t & 31) == 0) { ws[t >> 5][0] = s0; ws[t >> 5][1] = s1; }
    __syncthreads();
    if (t == 0) {
        float a = 0.f, bb = 0.f;
#pragma unroll
        for (int w = 0; w < 8; ++w) { a += ws[w][0]; bb += ws[w][1]; }
        g_gap[g0 + 0] = a  * (1.0f / (float)DHW);
        g_gap[g0 + 1] = bb * (1.0f / (float)DHW);
        __threadfence();                       // release
        atomicAdd(&g_done[b], 1);
    }
}

// ---------------------------------------------------------------------------
// M role: wait for batch's gap (acquire), read row from L2 (__ldcs), compute
// the 4 scores via block reduction, softmax over L, multiply, stream out.
// ---------------------------------------------------------------------------
__device__ __forceinline__ void mul_role(const float* __restrict__ in,
                                         const float* __restrict__ Wm,
                                         float* __restrict__ out, int b, int m) {
    const int l0 = m >> 8;                 // m in [0,1024)
    const int d  = m & 255;
    const int g  = (l0 * DB + b) * DC + d;
    const int t  = threadIdx.x;

    if (t == 0) {
        while (*((volatile int*)&g_done[b]) < GPB) __nanosleep(64);
        __threadfence();                       // acquire
    }
    __syncthreads();

    const size_t base = (size_t)g * VEC_PER_LBC;
    const float4* p = reinterpret_cast<const float4*>(in) + base;
    float4* q = reinterpret_cast<float4*>(out) + base;

    float4 v[4];
#pragma unroll
    for (int i = 0; i < 4; ++i) v[i] = __ldcs(&p[i * 256 + t]);   // L2-hot

    const float wv = __ldg(&Wm[d * DC + t]);
    float part[DL];
#pragma unroll
    for (int l = 0; l < DL; ++l) part[l] = wv * __ldcg(&g_gap[(l * DB + b) * DC + t]);

#pragma unroll
    for (int o = 16; o > 0; o >>= 1)
#pragma unroll
        for (int l = 0; l < DL; ++l) part[l] += __shfl_xor_sync(0xffffffffu, part[l], o);

    __shared__ float sred[8][DL];
    if ((t & 31) == 0) {
#pragma unroll
        for (int l = 0; l < DL; ++l) sred[t >> 5][l] = part[l];
    }
    __syncthreads();

    float sc[DL];
#pragma unroll
    for (int l = 0; l < DL; ++l) {
        float s = 0.f;
#pragma unroll
        for (int w8 = 0; w8 < 8; ++w8) s += sred[w8][l];
        sc[l] = s;
    }

    float mx = sc[0];
#pragma unroll
    for (int l = 1; l < DL; ++l) mx = fmaxf(mx, sc[l]);
    float sum = 0.f, el0 = 0.f;
#pragma unroll
    for (int l = 0; l < DL; ++l) {
        float e = __expf(sc[l] - mx);
        sum += e;
        if (l == l0) el0 = e;
    }
    const float a = el0 / sum;

#pragma unroll
    for (int i = 0; i < 4; ++i) {
        v[i].x *= a; v[i].y *= a; v[i].z *= a; v[i].w *= a;
        __stcs(&q[i * 256 + t], v[i]);
    }
}

// ---------------------------------------------------------------------------
// Single pipelined kernel. bid layout:
//   [0, 512)           : G(batch 0)
//   [512, 512+7*1536)  : segment k: 2:1 interleave of M(k) and G(k+1)
//   tail 1024          : M(batch 7)
// ---------------------------------------------------------------------------
__global__ void __launch_bounds__(256) pipeline_kernel(const float* __restrict__ in,
                                                       const float* __restrict__ Wm,
                                                       float* __restrict__ out) {
    int bid = blockIdx.x;
    if (bid < GPB) { gap_role(in, 0, bid); return; }
    bid -= GPB;
    if (bid < 7 * SEG) {
        const int k  = bid / SEG;
        const int r3 = bid - k * SEG;
        const int qq = r3 / 3;
        const int rr = r3 - 3 * qq;
        if (rr == 2) gap_role(in, k + 1, qq);
        else         mul_role(in, Wm, out, k, 2 * qq + rr);
        return;
    }
    bid -= 7 * SEG;
    mul_role(in, Wm, out, DB - 1, bid);
}

// ---------------------------------------------------------------------------
extern "C" void kernel_launch(void* const* d_in, const int* in_sizes, int n_in,
                              void* d_out, int out_size) {
    const float* in = (const float*)d_in[0];   // [L,B,C,H,W]
    const float* Wm = (const float*)d_in[1];   // [C,C]
    float* out = (float*)d_out;

    init_kernel<<<1, 32>>>();
    pipeline_kernel<<<TOTAL_BLOCKS, 256>>>(in, Wm, out);
}